// round 13
// baseline (speedup 1.0000x reference)
#include <cuda_runtime.h>
#include <cuda_bf16.h>
#include <math_constants.h>
#include <cstdint>

#define B_ 32
#define T_ 2048
#define D_ 512
#define BT (B_*T_)
#define BTD (BT*D_)

// ---- output layout ----
#define OFF_GR   0
#define OFF_SS   (OFF_GR + B_)
#define OFF_RM   (OFF_SS + B_*D_)
#define OFF_RV   (OFF_RM + B_)
#define OFF_COV  (OFF_RV + B_)
#define OFF_MASK (OFF_COV + B_)
#define OFF_LD   (OFF_MASK + BT)
#define OFF_REF  (OFF_LD + BT)
#define OFF_ATT  (OFF_REF + BT)
#define OFF_PRF  (OFF_ATT + BT)
#define OFF_CN   (OFF_PRF + BT)

// ---- scratch ----
__device__ __nv_bfloat16 g_xhi[BTD];
__device__ __nv_bfloat16 g_xlo[BTD];
__device__ __nv_bfloat16 g_yhi[BTD];
__device__ __nv_bfloat16 g_ylo[BTD];
__device__ float g_h0[BTD];                 // conv2 output fp32
__device__ __nv_bfloat16 g_w1hi[D_*3*D_];   // [o][j = k*512 + i]
__device__ __nv_bfloat16 g_w1lo[D_*3*D_];
__device__ __nv_bfloat16 g_w2hi[D_*3*D_];
__device__ __nv_bfloat16 g_w2lo[D_*3*D_];
__device__ float g_p1t[2*D_*D_];
__device__ float g_p2t[D_*D_];
__device__ float g_ps1[B_*16*D_];           // LN-stats partials
__device__ float g_ps2[B_*16*D_];
__device__ float g_support[B_];

__device__ __forceinline__ float gelu_f(float x) {
    return 0.5f * x * (1.0f + erff(x * 0.70710678118654752f));
}

// ============ portable PTX helpers ============
__device__ __forceinline__ uint32_t smem_u32(const void* p) {
    uint32_t a;
    asm("{ .reg .u64 t; cvta.to.shared.u64 t, %1; cvt.u32.u64 %0, t; }" : "=r"(a) : "l"(p));
    return a;
}
#define SWZ128(x) ((x) ^ (((x) >> 3) & 0x70))
__device__ __forceinline__ void cpa16(uint32_t dst, const void* src) {
    asm volatile("cp.async.cg.shared.global [%0], [%1], 16;" :: "r"(dst), "l"(src));
}
__device__ __forceinline__ void cpa_commit() { asm volatile("cp.async.commit_group;" ::: "memory"); }
__device__ __forceinline__ void cpa_wait0()  { asm volatile("cp.async.wait_group 0;" ::: "memory"); }
__device__ __forceinline__ void sts16_zero(uint32_t a) {
    asm volatile("st.shared.v4.b32 [%0], {%1,%1,%1,%1};" :: "r"(a), "r"(0) : "memory");
}
__device__ __forceinline__ void ldsm4(uint32_t* r, uint32_t addr) {
    asm volatile("ldmatrix.sync.aligned.m8n8.x4.shared.b16 {%0,%1,%2,%3}, [%4];"
        : "=r"(r[0]), "=r"(r[1]), "=r"(r[2]), "=r"(r[3]) : "r"(addr));
}
__device__ __forceinline__ void mma_bf16(float* d, const uint32_t* a, uint32_t b0, uint32_t b1) {
    asm volatile(
        "mma.sync.aligned.m16n8k16.row.col.f32.bf16.bf16.f32 "
        "{%0,%1,%2,%3}, {%4,%5,%6,%7}, {%8,%9}, {%0,%1,%2,%3};"
        : "+f"(d[0]), "+f"(d[1]), "+f"(d[2]), "+f"(d[3])
        : "r"(a[0]), "r"(a[1]), "r"(a[2]), "r"(a[3]), "r"(b0), "r"(b1));
}

// ============================================================
// Kernel 1: per-batch stats / median / cheap outputs
// ============================================================
__global__ void k_batch_stats(const float* __restrict__ dur,
                              const float* __restrict__ mask_in,
                              float* __restrict__ out) {
    int b = blockIdx.x, tid = threadIdx.x;
    __shared__ float sv[T_];
    __shared__ float sr[1024];
    const float* db = dur + b*T_;
    const float* mb = mask_in + b*T_;

    float accn = 0.f;
    for (int t = tid; t < T_; t += 1024) {
        float mk = fminf(fmaxf(mb[t], 0.f), 1.f);
        float ld = logf(fmaxf(db[t], 1e-4f)) * mk;
        out[OFF_MASK + b*T_ + t] = mk;
        out[OFF_LD   + b*T_ + t] = ld;
        sv[t] = (mk > 0.5f) ? ld : CUDART_INF_F;
        accn += mk;
    }
    sr[tid] = accn; __syncthreads();
    for (int s = 512; s > 0; s >>= 1) { if (tid < s) sr[tid] += sr[tid+s]; __syncthreads(); }
    float n = sr[0];
    __syncthreads();

    for (int k = 2; k <= T_; k <<= 1)
        for (int j = k >> 1; j > 0; j >>= 1) {
            for (int idx = tid; idx < T_; idx += 1024) {
                int ixj = idx ^ j;
                if (ixj > idx) {
                    float a = sv[idx], c = sv[ixj];
                    bool up = ((idx & k) == 0);
                    if ((a > c) == up) { sv[idx] = c; sv[ixj] = a; }
                }
            }
            __syncthreads();
        }

    int ni = (int)(n + 0.5f);
    float med = (ni > 0) ? sv[(ni - 1) >> 1] : 0.f;
    float support = fmaxf(n, 1.f);

    float acc1 = 0.f;
    for (int t = tid; t < T_; t += 1024) {
        float mk = out[OFF_MASK + b*T_ + t];
        float ld = out[OFF_LD   + b*T_ + t];
        float rr = (ld - med) * mk;
        out[OFF_REF + b*T_ + t] = rr;
        out[OFF_ATT + b*T_ + t] = mk / support;
        acc1 += rr;
    }
    sr[tid] = acc1; __syncthreads();
    for (int s = 512; s > 0; s >>= 1) { if (tid < s) sr[tid] += sr[tid+s]; __syncthreads(); }
    float rmean = sr[0] / support;
    __syncthreads();

    float acc2 = 0.f;
    for (int t = tid; t < T_; t += 1024) {
        float mk = out[OFF_MASK + b*T_ + t];
        float rr = out[OFF_REF  + b*T_ + t];
        float d = rr - rmean;
        acc2 += d * d * mk;
        out[OFF_PRF + b*T_ + t] = rmean * mk;
    }
    sr[tid] = acc2; __syncthreads();
    for (int s = 512; s > 0; s >>= 1) { if (tid < s) sr[tid] += sr[tid+s]; __syncthreads(); }

    if (tid == 0) {
        out[OFF_GR  + b] = med;
        out[OFF_RM  + b] = rmean;
        out[OFF_RV  + b] = fmaxf(sr[0] / support, 1e-4f);
        out[OFF_COV + b] = fmaxf(n / (float)T_, 0.05f);
        g_support[b] = n;
    }
}

// ============================================================
// Kernel 2: weight prep — bf16 hi/lo, layout [o][j=k*512+i]
// ============================================================
__global__ void k_prep(const float* __restrict__ c1, const float* __restrict__ c2,
                       const float* __restrict__ p1, const float* __restrict__ p2) {
    const int NW = D_*3*D_;
    const int total = 2*NW + 2*D_*D_ + D_*D_;
    for (int idx = blockIdx.x*blockDim.x + threadIdx.x; idx < total;
         idx += gridDim.x*blockDim.x) {
        if (idx < 2*NW) {
            int r = (idx < NW) ? idx : idx - NW;
            int o = r / (3*D_), j = r % (3*D_);
            int i = j & (D_-1), k = j >> 9;
            float v = (idx < NW) ? c1[o*(3*D_) + i*3 + k] : c2[o*(3*D_) + i*3 + k];
            __nv_bfloat16 hi = __float2bfloat16(v);
            __nv_bfloat16 lo = __float2bfloat16(v - __bfloat162float(hi));
            if (idx < NW) { g_w1hi[r] = hi; g_w1lo[r] = lo; }
            else          { g_w2hi[r] = hi; g_w2lo[r] = lo; }
        } else if (idx < 2*NW + 2*D_*D_) {
            int r = idx - 2*NW;
            int j = r / D_, d = r % D_;
            g_p1t[r] = p1[d*(2*D_) + j];
        } else {
            int r = idx - (2*NW + 2*D_*D_);
            int j = r / D_, d = r % D_;
            g_p2t[r] = p2[d*D_ + j];
        }
    }
}

// ============================================================
// Kernel 3: h0 -> bf16 hi/lo split
// ============================================================
__global__ void k_hidden0(const int* __restrict__ ids,
                          const float* __restrict__ emb,
                          const float* __restrict__ aux_w,
                          const float* __restrict__ aux_b,
                          const float* __restrict__ out) {
    int gid = blockIdx.x*blockDim.x + threadIdx.x;
    int tok = gid >> 7, dv = gid & 127;
    int id = ids[tok];
    float rr = out[OFF_REF + tok];
    float4 e = ((const float4*)emb)[id*(D_/4) + dv];
    float4 w = ((const float4*)aux_w)[dv];
    float4 bb = ((const float4*)aux_b)[dv];
    float h[4];
    h[0] = e.x + rr*w.x + bb.x;
    h[1] = e.y + rr*w.y + bb.y;
    h[2] = e.z + rr*w.z + bb.z;
    h[3] = e.w + rr*w.w + bb.w;
    __nv_bfloat16 hi[4], lo[4];
    #pragma unroll
    for (int q = 0; q < 4; ++q) {
        hi[q] = __float2bfloat16(h[q]);
        lo[q] = __float2bfloat16(h[q] - __bfloat162float(hi[q]));
    }
    ((uint2*)g_xhi)[gid] = *(uint2*)hi;
    ((uint2*)g_xlo)[gid] = *(uint2*)lo;
}

// ============================================================
// Kernel 4: causal conv via mma.sync bf16 split (3 passes)
//   CTA 256(M) x 128(N), 512 threads (16 warps, 4x4 grid),
//   K=1536 in 24 chunks of 64, 2-stage pipeline.
//   Incremental source pointers: +128 B/chunk uniformly.
// ============================================================
#define CHUNKS 24
#define TA   32768                // A tile: 256 rows x 128B
#define TB   16384                // B tile: 128 rows x 128B
#define AHI  0
#define ALO  (AHI + TA)
#define BHI  (ALO + TA)
#define BLO  (BHI + TB)
#define BUFB (BLO + TB)           // 98304
#define STAGE_STRIDE 0x20000      // 128 KB (power-of-2 for cheap parity add)

__global__ void __launch_bounds__(512, 1) k_conv_mma(int which, const float* __restrict__ bias) {
    const __nv_bfloat16* Xhi = which ? g_yhi : g_xhi;
    const __nv_bfloat16* Xlo = which ? g_ylo : g_xlo;
    const __nv_bfloat16* Whi = which ? g_w2hi : g_w1hi;
    const __nv_bfloat16* Wlo = which ? g_w2lo : g_w1lo;

    extern __shared__ char smem_raw[];
    uint32_t sbase = (smem_u32(smem_raw) + 1023) & ~1023u;

    int tid = threadIdx.x;
    int wid = tid >> 5, lane = tid & 31;
    int wm = wid >> 2, wn = wid & 3;       // warp grid 4(M) x 4(N)

    int bt0   = blockIdx.x * 256;
    int o0    = blockIdx.y * 128;
    int batch = bt0 / T_;
    int tloc0 = bt0 - batch * T_;

    float acc[4][4][4] = {};

    // ---- persistent incremental load state ----
    const char* pA[4];          // Xhi source per A-quarter (tap0 position)
    uint32_t dA[4];             // smem dst offset (buffer 0, AHI tile)
    int rowtokA[4];             // tloc0 + row  (valid for tap iff rowtok+tap >= 2)
    const char* pB[2];
    uint32_t dB[2];
    const ptrdiff_t dXlo = (const char*)Xlo - (const char*)Xhi;
    const ptrdiff_t dWlo = (const char*)Wlo - (const char*)Whi;

    #pragma unroll
    for (int q = 0; q < 4; ++q) {
        int flat = q * 512 + tid;
        int row = flat >> 3, c16 = flat & 7;
        dA[q] = AHI + SWZ128((uint32_t)(row * 128 + c16 * 16));
        rowtokA[q] = tloc0 + row;
        // tap0 source token = batch*T_ + tloc0 + row - 2 (may be "negative"; never deref then)
        pA[q] = (const char*)(Xhi + (ptrdiff_t)(batch*T_ + tloc0 + row - 2)*D_ + c16*8);
    }
    #pragma unroll
    for (int q = 0; q < 2; ++q) {
        int flat = q * 512 + tid;
        int row = flat >> 3, c16 = flat & 7;
        dB[q] = BHI + SWZ128((uint32_t)(row * 128 + c16 * 16));
        pB[q] = (const char*)(Whi + (size_t)(o0 + row)*(3*D_) + c16*8);
    }

    auto load_chunk = [&](int c) {
        uint32_t po = sbase + ((uint32_t)(c & 1) << 17);
        int tap = c >> 3;
        #pragma unroll
        for (int q = 0; q < 4; ++q) {
            uint32_t d0 = po + dA[q];
            if (rowtokA[q] + tap >= 2) {
                cpa16(d0,      pA[q]);
                cpa16(d0 + TA, pA[q] + dXlo);
            } else {
                sts16_zero(d0);
                sts16_zero(d0 + TA);
            }
            pA[q] += 128;
        }
        #pragma unroll
        for (int q = 0; q < 2; ++q) {
            uint32_t d0 = po + dB[q];
            cpa16(d0,      pB[q]);
            cpa16(d0 + TB, pB[q] + dWlo);
            pB[q] += 128;
        }
        cpa_commit();
    };

    load_chunk(0);

    int lr = lane & 15;
    uint32_t L16 = (uint32_t)((lane >> 4) << 4);

    uint32_t aHo[4], bHo[2];
    #pragma unroll
    for (int mt = 0; mt < 4; ++mt) {
        uint32_t row = (uint32_t)(wm*64 + mt*16 + lr);
        aHo[mt] = AHI + ((row * 128u) | (L16 ^ ((row & 7u) << 4)));
    }
    #pragma unroll
    for (int np = 0; np < 2; ++np) {
        uint32_t row = (uint32_t)(wn*32 + np*16 + lr);
        bHo[np] = BHI + ((row * 128u) | (L16 ^ ((row & 7u) << 4)));
    }

    for (int c = 0; c < CHUNKS; ++c) {
        cpa_wait0();                   // chunk c resident
        __syncthreads();               // all warps done with chunk c-1's buffer
        if (c + 1 < CHUNKS) load_chunk(c + 1);

        uint32_t bufb = sbase + ((uint32_t)(c & 1) << 17);
        uint32_t baH[4], bbH[2];
        #pragma unroll
        for (int mt = 0; mt < 4; ++mt) baH[mt] = bufb + aHo[mt];
        #pragma unroll
        for (int np = 0; np < 2; ++np) bbH[np] = bufb + bHo[np];

        #pragma unroll
        for (int ks = 0; ks < 4; ++ks) {
            const uint32_t Kc = (uint32_t)(ks * 32);
            uint32_t ah[4][4], al[4][4], bh[2][4], bl[2][4];
            #pragma unroll
            for (int mt = 0; mt < 4; ++mt) ldsm4(ah[mt], baH[mt] ^ Kc);
            #pragma unroll
            for (int np = 0; np < 2; ++np) ldsm4(bh[np], bbH[np] ^ Kc);
            #pragma unroll
            for (int mt = 0; mt < 4; ++mt)
                #pragma unroll
                for (int nt = 0; nt < 4; ++nt)
                    mma_bf16(acc[mt][nt], ah[mt], bh[nt>>1][nt&1], bh[nt>>1][(nt&1)+2]);
            #pragma unroll
            for (int mt = 0; mt < 4; ++mt) ldsm4(al[mt], (baH[mt] + TA) ^ Kc);
            #pragma unroll
            for (int mt = 0; mt < 4; ++mt)
                #pragma unroll
                for (int nt = 0; nt < 4; ++nt)
                    mma_bf16(acc[mt][nt], al[mt], bh[nt>>1][nt&1], bh[nt>>1][(nt&1)+2]);
            #pragma unroll
            for (int np = 0; np < 2; ++np) ldsm4(bl[np], (bbH[np] + TB) ^ Kc);
            #pragma unroll
            for (int mt = 0; mt < 4; ++mt)
                #pragma unroll
                for (int nt = 0; nt < 4; ++nt)
                    mma_bf16(acc[mt][nt], ah[mt], bl[nt>>1][nt&1], bl[nt>>1][(nt&1)+2]);
        }
    }

    // ---- epilogue: bias + GELU, direct stores ----
    #pragma unroll
    for (int mt = 0; mt < 4; ++mt) {
        #pragma unroll
        for (int nt = 0; nt < 4; ++nt) {
            int row = bt0 + wm*64 + mt*16 + (lane >> 2);
            int col = o0 + wn*32 + nt*8 + (lane & 3)*2;
            float b0 = bias[col], b1 = bias[col+1];
            #pragma unroll
            for (int half = 0; half < 2; ++half) {
                int r = row + half*8;
                float y0 = gelu_f(acc[mt][nt][half*2+0] + b0);
                float y1 = gelu_f(acc[mt][nt][half*2+1] + b1);
                size_t off = (size_t)r * D_ + col;
                if (which == 0) {
                    __nv_bfloat16 h0 = __float2bfloat16(y0);
                    __nv_bfloat16 h1 = __float2bfloat16(y1);
                    __nv_bfloat16 l0 = __float2bfloat16(y0 - __bfloat162float(h0));
                    __nv_bfloat16 l1 = __float2bfloat16(y1 - __bfloat162float(h1));
                    *(__nv_bfloat162*)(g_yhi + off) = __nv_bfloat162(h0, h1);
                    *(__nv_bfloat162*)(g_ylo + off) = __nv_bfloat162(l0, l1);
                } else {
                    *(float2*)(g_h0 + off) = make_float2(y0, y1);
                }
            }
        }
    }
}

// ============================================================
// Kernel 5 (fused): LayerNorm * mask + per-channel partial stats
// ============================================================
__global__ void __launch_bounds__(256) k_ln_stats(const float* __restrict__ g,
                                                  const float* __restrict__ bta,
                                                  const float* __restrict__ out) {
    int b = blockIdx.x >> 4, chunk = blockIdx.x & 15;
    int tid = threadIdx.x, wid = tid >> 5, lane = tid & 31;
    __shared__ float s1s[8][D_];
    __shared__ float s2s[8][D_];

    float gd[16], bd[16];
    #pragma unroll
    for (int l = 0; l < 16; ++l) { gd[l] = g[l*32 + lane]; bd[l] = bta[l*32 + lane]; }

    float a1[16] = {}, a2[16] = {};
    int tokbase = b*T_ + chunk*128 + wid*16;

    for (int i = 0; i < 16; ++i) {
        int tok = tokbase + i;
        const float* x = g_h0 + (size_t)tok * D_;
        float v[16], s = 0.f;
        #pragma unroll
        for (int l = 0; l < 16; ++l) { v[l] = x[l*32 + lane]; s += v[l]; }
        #pragma unroll
        for (int o = 16; o; o >>= 1) s += __shfl_xor_sync(0xffffffffu, s, o);
        float mean = s * (1.f / D_);
        float sq = 0.f;
        #pragma unroll
        for (int l = 0; l < 16; ++l) { float d = v[l] - mean; sq += d*d; }
        #pragma unroll
        for (int o = 16; o; o >>= 1) sq += __shfl_xor_sync(0xffffffffu, sq, o);
        float inv = rsqrtf(sq * (1.f / D_) + 1e-5f);
        float mk = out[OFF_MASK + tok];
        #pragma unroll
        for (int l = 0; l < 16; ++l) {
            float y = ((v[l] - mean) * inv * gd[l] + bd[l]) * mk;
            a1[l] += y; a2[l] += y*y;
        }
    }
    #pragma unroll
    for (int l = 0; l < 16; ++l) { s1s[wid][l*32 + lane] = a1[l]; s2s[wid][l*32 + lane] = a2[l]; }
    __syncthreads();
    for (int d = tid; d < D_; d += 256) {
        float t1 = 0.f, t2 = 0.f;
        #pragma unroll
        for (int w = 0; w < 8; ++w) { t1 += s1s[w][d]; t2 += s2s[w][d]; }
        g_ps1[(b*16 + chunk)*D_ + d] = t1;
        g_ps2[(b*16 + chunk)*D_ + d] = t2;
    }
}

// ============================================================
// Kernel 6: MLP head (folds final stats reduction into prologue)
// ============================================================
__global__ void __launch_bounds__(512) k_mlp(const float* __restrict__ p1b,
                                             const float* __restrict__ p2b,
                                             float* __restrict__ out) {
    int b = blockIdx.x, tid = threadIdx.x;
    __shared__ float h[1024];
    __shared__ float a[512];
    __shared__ float red[512];

    float S1 = 0.f, S2 = 0.f;
    #pragma unroll
    for (int c = 0; c < 16; ++c) {
        S1 += g_ps1[(b*16 + c)*D_ + tid];
        S2 += g_ps2[(b*16 + c)*D_ + tid];
    }
    float n = g_support[b];
    float denom = fmaxf(n, 1.f);
    float mean = S1 / denom;
    float varsum = S2 - 2.f*mean*S1 + mean*mean*n;
    h[tid]       = mean;
    h[tid + 512] = sqrtf(varsum / denom + 1e-6f);
    __syncthreads();

    float acc = 0.f;
    #pragma unroll 4
    for (int j = 0; j < 1024; ++j) acc += h[j] * g_p1t[j*D_ + tid];
    a[tid] = gelu_f(acc + p1b[tid]);
    __syncthreads();
    float acc2 = 0.f;
    #pragma unroll 4
    for (int j = 0; j < 512; ++j) acc2 += a[j] * g_p2t[j*D_ + tid];
    float s = tanhf(acc2 + p2b[tid]);
    if (n <= 0.f) s = 0.f;
    out[OFF_SS + b*D_ + tid] = s;
    red[tid] = s*s; __syncthreads();
    for (int st = 256; st; st >>= 1) { if (tid < st) red[tid] += red[tid+st]; __syncthreads(); }
    if (tid == 0) out[OFF_CN + b] = sqrtf(red[0]);
}

// ============================================================
extern "C" void kernel_launch(void* const* d_in, const int* in_sizes, int n_in,
                              void* d_out, int out_size) {
    const int*   ids   = (const int*)  d_in[0];
    const float* dur   = (const float*)d_in[1];
    const float* maskp = (const float*)d_in[2];
    const float* emb   = (const float*)d_in[3];
    const float* aux_w = (const float*)d_in[4];
    const float* aux_b = (const float*)d_in[5];
    const float* c1w   = (const float*)d_in[6];
    const float* c1b   = (const float*)d_in[7];
    const float* c2w   = (const float*)d_in[8];
    const float* c2b   = (const float*)d_in[9];
    const float* lng   = (const float*)d_in[10];
    const float* lnb   = (const float*)d_in[11];
    const float* p1w   = (const float*)d_in[12];
    const float* p1b   = (const float*)d_in[13];
    const float* p2w   = (const float*)d_in[14];
    const float* p2b   = (const float*)d_in[15];
    float* out = (float*)d_out;

    size_t shmem = 1024 + STAGE_STRIDE + BUFB;   // 230400 B
    cudaFuncSetAttribute(k_conv_mma, cudaFuncAttributeMaxDynamicSharedMemorySize, (int)shmem);

    k_prep<<<256, 256>>>(c1w, c2w, p1w, p2w);
    k_batch_stats<<<B_, 1024>>>(dur, maskp, out);
    k_hidden0<<<(BT*(D_/4))/256, 256>>>(ids, emb, aux_w, aux_b, out);

    dim3 gconv(BT/256, D_/128);
    k_conv_mma<<<gconv, 512, shmem>>>(0, c1b);
    k_conv_mma<<<gconv, 512, shmem>>>(1, c2b);

    k_ln_stats<<<B_*16, 256>>>(lng, lnb, out);
    k_mlp<<<B_, 512>>>(p1b, p2b, out);
}

// round 15
// speedup vs baseline: 1.4845x; 1.4845x over previous
#include <cuda_runtime.h>
#include <cuda_fp16.h>
#include <math_constants.h>
#include <cstdint>

#define B_ 32
#define T_ 2048
#define D_ 512
#define BT (B_*T_)
#define BTD (BT*D_)

// ---- output layout ----
#define OFF_GR   0
#define OFF_SS   (OFF_GR + B_)
#define OFF_RM   (OFF_SS + B_*D_)
#define OFF_RV   (OFF_RM + B_)
#define OFF_COV  (OFF_RV + B_)
#define OFF_MASK (OFF_COV + B_)
#define OFF_LD   (OFF_MASK + BT)
#define OFF_REF  (OFF_LD + BT)
#define OFF_ATT  (OFF_REF + BT)
#define OFF_PRF  (OFF_ATT + BT)
#define OFF_CN   (OFF_PRF + BT)

// ---- scratch ----
__device__ __half g_x[BTD];                 // conv1 input, fp16
__device__ __half g_y[BTD];                 // conv1 output / conv2 input, fp16
__device__ float  g_h0[BTD];                // conv2 output fp32
__device__ __half g_w1hi[D_*3*D_];          // [o][j = k*512 + i]
__device__ __half g_w1lo[D_*3*D_];
__device__ __half g_w2hi[D_*3*D_];
__device__ __half g_w2lo[D_*3*D_];
__device__ float g_p1t[2*D_*D_];
__device__ float g_p2t[D_*D_];
__device__ float g_ps1[B_*16*D_];           // LN-stats partials
__device__ float g_ps2[B_*16*D_];
__device__ float g_support[B_];

__device__ __forceinline__ float gelu_f(float x) {
    return 0.5f * x * (1.0f + erff(x * 0.70710678118654752f));
}

// ============ portable PTX helpers ============
__device__ __forceinline__ uint32_t smem_u32(const void* p) {
    uint32_t a;
    asm("{ .reg .u64 t; cvta.to.shared.u64 t, %1; cvt.u32.u64 %0, t; }" : "=r"(a) : "l"(p));
    return a;
}
#define SWZ128(x) ((x) ^ (((x) >> 3) & 0x70))
__device__ __forceinline__ void cpa16(uint32_t dst, const void* src) {
    asm volatile("cp.async.cg.shared.global [%0], [%1], 16;" :: "r"(dst), "l"(src));
}
__device__ __forceinline__ void cpa_commit() { asm volatile("cp.async.commit_group;" ::: "memory"); }
__device__ __forceinline__ void cpa_wait1()  { asm volatile("cp.async.wait_group 1;" ::: "memory"); }
__device__ __forceinline__ void cpa_wait0()  { asm volatile("cp.async.wait_group 0;" ::: "memory"); }
__device__ __forceinline__ void ldsm4(uint32_t* r, uint32_t addr) {
    asm volatile("ldmatrix.sync.aligned.m8n8.x4.shared.b16 {%0,%1,%2,%3}, [%4];"
        : "=r"(r[0]), "=r"(r[1]), "=r"(r[2]), "=r"(r[3]) : "r"(addr));
}
__device__ __forceinline__ void mma_f16(float* d, const uint32_t* a, uint32_t b0, uint32_t b1) {
    asm volatile(
        "mma.sync.aligned.m16n8k16.row.col.f32.f16.f16.f32 "
        "{%0,%1,%2,%3}, {%4,%5,%6,%7}, {%8,%9}, {%0,%1,%2,%3};"
        : "+f"(d[0]), "+f"(d[1]), "+f"(d[2]), "+f"(d[3])
        : "r"(a[0]), "r"(a[1]), "r"(a[2]), "r"(a[3]), "r"(b0), "r"(b1));
}

// ============================================================
// Kernel 1: per-batch stats / median / cheap outputs
// ============================================================
__global__ void k_batch_stats(const float* __restrict__ dur,
                              const float* __restrict__ mask_in,
                              float* __restrict__ out) {
    int b = blockIdx.x, tid = threadIdx.x;
    __shared__ float sv[T_];
    __shared__ float sr[1024];
    const float* db = dur + b*T_;
    const float* mb = mask_in + b*T_;

    float accn = 0.f;
    for (int t = tid; t < T_; t += 1024) {
        float mk = fminf(fmaxf(mb[t], 0.f), 1.f);
        float ld = logf(fmaxf(db[t], 1e-4f)) * mk;
        out[OFF_MASK + b*T_ + t] = mk;
        out[OFF_LD   + b*T_ + t] = ld;
        sv[t] = (mk > 0.5f) ? ld : CUDART_INF_F;
        accn += mk;
    }
    sr[tid] = accn; __syncthreads();
    for (int s = 512; s > 0; s >>= 1) { if (tid < s) sr[tid] += sr[tid+s]; __syncthreads(); }
    float n = sr[0];
    __syncthreads();

    for (int k = 2; k <= T_; k <<= 1)
        for (int j = k >> 1; j > 0; j >>= 1) {
            for (int idx = tid; idx < T_; idx += 1024) {
                int ixj = idx ^ j;
                if (ixj > idx) {
                    float a = sv[idx], c = sv[ixj];
                    bool up = ((idx & k) == 0);
                    if ((a > c) == up) { sv[idx] = c; sv[ixj] = a; }
                }
            }
            __syncthreads();
        }

    int ni = (int)(n + 0.5f);
    float med = (ni > 0) ? sv[(ni - 1) >> 1] : 0.f;
    float support = fmaxf(n, 1.f);

    float acc1 = 0.f;
    for (int t = tid; t < T_; t += 1024) {
        float mk = out[OFF_MASK + b*T_ + t];
        float ld = out[OFF_LD   + b*T_ + t];
        float rr = (ld - med) * mk;
        out[OFF_REF + b*T_ + t] = rr;
        out[OFF_ATT + b*T_ + t] = mk / support;
        acc1 += rr;
    }
    sr[tid] = acc1; __syncthreads();
    for (int s = 512; s > 0; s >>= 1) { if (tid < s) sr[tid] += sr[tid+s]; __syncthreads(); }
    float rmean = sr[0] / support;
    __syncthreads();

    float acc2 = 0.f;
    for (int t = tid; t < T_; t += 1024) {
        float mk = out[OFF_MASK + b*T_ + t];
        float rr = out[OFF_REF  + b*T_ + t];
        float d = rr - rmean;
        acc2 += d * d * mk;
        out[OFF_PRF + b*T_ + t] = rmean * mk;
    }
    sr[tid] = acc2; __syncthreads();
    for (int s = 512; s > 0; s >>= 1) { if (tid < s) sr[tid] += sr[tid+s]; __syncthreads(); }

    if (tid == 0) {
        out[OFF_GR  + b] = med;
        out[OFF_RM  + b] = rmean;
        out[OFF_RV  + b] = fmaxf(sr[0] / support, 1e-4f);
        out[OFF_COV + b] = fmaxf(n / (float)T_, 0.05f);
        g_support[b] = n;
    }
}

// ============================================================
// Kernel 2: weight prep — fp16 hi/lo split, layout [o][j=k*512+i]
// ============================================================
__global__ void k_prep(const float* __restrict__ c1, const float* __restrict__ c2,
                       const float* __restrict__ p1, const float* __restrict__ p2) {
    const int NW = D_*3*D_;
    const int total = 2*NW + 2*D_*D_ + D_*D_;
    for (int idx = blockIdx.x*blockDim.x + threadIdx.x; idx < total;
         idx += gridDim.x*blockDim.x) {
        if (idx < 2*NW) {
            int r = (idx < NW) ? idx : idx - NW;
            int o = r / (3*D_), j = r % (3*D_);
            int i = j & (D_-1), k = j >> 9;
            float v = (idx < NW) ? c1[o*(3*D_) + i*3 + k] : c2[o*(3*D_) + i*3 + k];
            __half hi = __float2half_rn(v);
            __half lo = __float2half_rn(v - __half2float(hi));
            if (idx < NW) { g_w1hi[r] = hi; g_w1lo[r] = lo; }
            else          { g_w2hi[r] = hi; g_w2lo[r] = lo; }
        } else if (idx < 2*NW + 2*D_*D_) {
            int r = idx - 2*NW;
            int j = r / D_, d = r % D_;
            g_p1t[r] = p1[d*(2*D_) + j];
        } else {
            int r = idx - (2*NW + 2*D_*D_);
            int j = r / D_, d = r % D_;
            g_p2t[r] = p2[d*D_ + j];
        }
    }
}

// ============================================================
// Kernel 3: h0 -> fp16
// ============================================================
__global__ void k_hidden0(const int* __restrict__ ids,
                          const float* __restrict__ emb,
                          const float* __restrict__ aux_w,
                          const float* __restrict__ aux_b,
                          const float* __restrict__ out) {
    int gid = blockIdx.x*blockDim.x + threadIdx.x;
    int tok = gid >> 7, dv = gid & 127;
    int id = ids[tok];
    float rr = out[OFF_REF + tok];
    float4 e = ((const float4*)emb)[id*(D_/4) + dv];
    float4 w = ((const float4*)aux_w)[dv];
    float4 bb = ((const float4*)aux_b)[dv];
    __half h[4];
    h[0] = __float2half_rn(e.x + rr*w.x + bb.x);
    h[1] = __float2half_rn(e.y + rr*w.y + bb.y);
    h[2] = __float2half_rn(e.z + rr*w.z + bb.z);
    h[3] = __float2half_rn(e.w + rr*w.w + bb.w);
    ((uint2*)g_x)[gid] = *(uint2*)h;
}

// ============================================================
// Kernel 4: causal conv via fp16 mma.sync, weight hi/lo (2 passes)
//   CTA 256(M) x 128(N), 512 threads (16 warps, 4x4 grid),
//   K=1536 in 24 chunks of 64, 3-stage pipeline (64KB/stage)
// ============================================================
#define CHUNKS 24
#define TA   32768                // A tile: 256 rows x 128B (fp16 X)
#define TW   16384                // W tile: 128 rows x 128B
#define AOFF 0
#define WHI  (AOFF + TA)
#define WLO  (WHI + TW)
#define BUFB (WLO + TW)           // 65536 per stage
#define NSTAGE 3

__global__ void __launch_bounds__(512, 1) k_conv_mma(int which, const float* __restrict__ bias) {
    const __half* X   = which ? g_y    : g_x;
    const __half* Whi = which ? g_w2hi : g_w1hi;
    const __half* Wlo = which ? g_w2lo : g_w1lo;

    extern __shared__ char smem_raw[];
    uint32_t sbase0 = smem_u32(smem_raw);
    uint32_t sbase = (sbase0 + 1023) & ~1023u;

    int tid = threadIdx.x;
    int wid = tid >> 5, lane = tid & 31;
    int wm = wid >> 2, wn = wid & 3;       // warp grid 4(M) x 4(N)

    int bt0   = blockIdx.x * 256;
    int o0    = blockIdx.y * 128;
    int batch = bt0 / T_;
    int tloc0 = bt0 - batch * T_;

    float acc[4][4][4] = {};

    auto load_chunk = [&](int c) {
        int j0 = c * 64;
        int kk = j0 >> 9;
        int i0 = j0 & 511;
        uint32_t bufb = sbase + (uint32_t)(c % NSTAGE) * BUFB;
        // A tile: 256 rows x 8 x 16B = 2048 transfers
        #pragma unroll
        for (int q = 0; q < 4; ++q) {
            int flat = q * 512 + tid;
            int row = flat >> 3, c16 = flat & 7;
            uint32_t swo = SWZ128((uint32_t)(row * 128 + c16 * 16));
            int st = tloc0 + row + kk - 2;
            if (st >= 0) {
                cpa16(bufb + AOFF + swo, X + (size_t)(batch*T_ + st)*D_ + i0 + c16*8);
            } else {
                *(uint4*)(smem_raw + (bufb - sbase0) + AOFF + swo) = make_uint4(0,0,0,0);
            }
        }
        // W tiles: 128 rows x 8 x 16B = 1024 transfers each plane
        #pragma unroll
        for (int q = 0; q < 2; ++q) {
            int flat = q * 512 + tid;
            int row = flat >> 3, c16 = flat & 7;
            uint32_t swo = SWZ128((uint32_t)(row * 128 + c16 * 16));
            const size_t src = (size_t)(o0 + row)*(3*D_) + j0 + c16*8;
            cpa16(bufb + WHI + swo, Whi + src);
            cpa16(bufb + WLO + swo, Wlo + src);
        }
        cpa_commit();
    };

    load_chunk(0);
    load_chunk(1);

    int lr = lane & 15;
    uint32_t L16 = (uint32_t)((lane >> 4) << 4);

    uint32_t aHo[4], bHo[2];
    #pragma unroll
    for (int mt = 0; mt < 4; ++mt) {
        uint32_t row = (uint32_t)(wm*64 + mt*16 + lr);
        aHo[mt] = AOFF + ((row * 128u) | (L16 ^ ((row & 7u) << 4)));
    }
    #pragma unroll
    for (int np = 0; np < 2; ++np) {
        uint32_t row = (uint32_t)(wn*32 + np*16 + lr);
        bHo[np] = WHI + ((row * 128u) | (L16 ^ ((row & 7u) << 4)));
    }

    for (int c = 0; c < CHUNKS; ++c) {
        if (c + 1 < CHUNKS) cpa_wait1(); else cpa_wait0();   // chunk c resident
        __syncthreads();               // all warps done with the stage being reloaded
        if (c + 2 < CHUNKS) load_chunk(c + 2);

        uint32_t bufb = sbase + (uint32_t)(c % NSTAGE) * BUFB;
        uint32_t baH[4], bbH[2];
        #pragma unroll
        for (int mt = 0; mt < 4; ++mt) baH[mt] = bufb + aHo[mt];
        #pragma unroll
        for (int np = 0; np < 2; ++np) bbH[np] = bufb + bHo[np];

        #pragma unroll
        for (int ks = 0; ks < 4; ++ks) {
            const uint32_t Kc = (uint32_t)(ks * 32);
            uint32_t a[4][4], bh[2][4], bl[2][4];
            #pragma unroll
            for (int mt = 0; mt < 4; ++mt) ldsm4(a[mt], baH[mt] ^ Kc);
            #pragma unroll
            for (int np = 0; np < 2; ++np) ldsm4(bh[np], bbH[np] ^ Kc);
            #pragma unroll
            for (int mt = 0; mt < 4; ++mt)
                #pragma unroll
                for (int nt = 0; nt < 4; ++nt)
                    mma_f16(acc[mt][nt], a[mt], bh[nt>>1][nt&1], bh[nt>>1][(nt&1)+2]);
            #pragma unroll
            for (int np = 0; np < 2; ++np) ldsm4(bl[np], (bbH[np] + TW) ^ Kc);
            #pragma unroll
            for (int mt = 0; mt < 4; ++mt)
                #pragma unroll
                for (int nt = 0; nt < 4; ++nt)
                    mma_f16(acc[mt][nt], a[mt], bl[nt>>1][nt&1], bl[nt>>1][(nt&1)+2]);
        }
    }

    // ---- epilogue: bias + GELU, direct stores ----
    #pragma unroll
    for (int mt = 0; mt < 4; ++mt) {
        #pragma unroll
        for (int nt = 0; nt < 4; ++nt) {
            int row = bt0 + wm*64 + mt*16 + (lane >> 2);
            int col = o0 + wn*32 + nt*8 + (lane & 3)*2;
            float b0 = bias[col], b1 = bias[col+1];
            #pragma unroll
            for (int half = 0; half < 2; ++half) {
                int r = row + half*8;
                float y0 = gelu_f(acc[mt][nt][half*2+0] + b0);
                float y1 = gelu_f(acc[mt][nt][half*2+1] + b1);
                size_t off = (size_t)r * D_ + col;
                if (which == 0) {
                    __half h0 = __float2half_rn(y0);
                    __half h1 = __float2half_rn(y1);
                    *(__half2*)(g_y + off) = __half2(h0, h1);
                } else {
                    *(float2*)(g_h0 + off) = make_float2(y0, y1);
                }
            }
        }
    }
}

// ============================================================
// Kernel 5 (fused): LayerNorm * mask + per-channel partial stats
// ============================================================
__global__ void __launch_bounds__(256) k_ln_stats(const float* __restrict__ g,
                                                  const float* __restrict__ bta,
                                                  const float* __restrict__ out) {
    int b = blockIdx.x >> 4, chunk = blockIdx.x & 15;
    int tid = threadIdx.x, wid = tid >> 5, lane = tid & 31;
    __shared__ float s1s[8][D_];
    __shared__ float s2s[8][D_];

    float gd[16], bd[16];
    #pragma unroll
    for (int l = 0; l < 16; ++l) { gd[l] = g[l*32 + lane]; bd[l] = bta[l*32 + lane]; }

    float a1[16] = {}, a2[16] = {};
    int tokbase = b*T_ + chunk*128 + wid*16;

    for (int i = 0; i < 16; ++i) {
        int tok = tokbase + i;
        const float* x = g_h0 + (size_t)tok * D_;
        float v[16], s = 0.f;
        #pragma unroll
        for (int l = 0; l < 16; ++l) { v[l] = x[l*32 + lane]; s += v[l]; }
        #pragma unroll
        for (int o = 16; o; o >>= 1) s += __shfl_xor_sync(0xffffffffu, s, o);
        float mean = s * (1.f / D_);
        float sq = 0.f;
        #pragma unroll
        for (int l = 0; l < 16; ++l) { float d = v[l] - mean; sq += d*d; }
        #pragma unroll
        for (int o = 16; o; o >>= 1) sq += __shfl_xor_sync(0xffffffffu, sq, o);
        float inv = rsqrtf(sq * (1.f / D_) + 1e-5f);
        float mk = out[OFF_MASK + tok];
        #pragma unroll
        for (int l = 0; l < 16; ++l) {
            float y = ((v[l] - mean) * inv * gd[l] + bd[l]) * mk;
            a1[l] += y; a2[l] += y*y;
        }
    }
    #pragma unroll
    for (int l = 0; l < 16; ++l) { s1s[wid][l*32 + lane] = a1[l]; s2s[wid][l*32 + lane] = a2[l]; }
    __syncthreads();
    for (int d = tid; d < D_; d += 256) {
        float t1 = 0.f, t2 = 0.f;
        #pragma unroll
        for (int w = 0; w < 8; ++w) { t1 += s1s[w][d]; t2 += s2s[w][d]; }
        g_ps1[(b*16 + chunk)*D_ + d] = t1;
        g_ps2[(b*16 + chunk)*D_ + d] = t2;
    }
}

// ============================================================
// Kernel 6: MLP head (folds final stats reduction into prologue)
// ============================================================
__global__ void __launch_bounds__(512) k_mlp(const float* __restrict__ p1b,
                                             const float* __restrict__ p2b,
                                             float* __restrict__ out) {
    int b = blockIdx.x, tid = threadIdx.x;
    __shared__ float h[1024];
    __shared__ float a[512];
    __shared__ float red[512];

    float S1 = 0.f, S2 = 0.f;
    #pragma unroll
    for (int c = 0; c < 16; ++c) {
        S1 += g_ps1[(b*16 + c)*D_ + tid];
        S2 += g_ps2[(b*16 + c)*D_ + tid];
    }
    float n = g_support[b];
    float denom = fmaxf(n, 1.f);
    float mean = S1 / denom;
    float varsum = S2 - 2.f*mean*S1 + mean*mean*n;
    h[tid]       = mean;
    h[tid + 512] = sqrtf(varsum / denom + 1e-6f);
    __syncthreads();

    float acc = 0.f;
    #pragma unroll 4
    for (int j = 0; j < 1024; ++j) acc += h[j] * g_p1t[j*D_ + tid];
    a[tid] = gelu_f(acc + p1b[tid]);
    __syncthreads();
    float acc2 = 0.f;
    #pragma unroll 4
    for (int j = 0; j < 512; ++j) acc2 += a[j] * g_p2t[j*D_ + tid];
    float s = tanhf(acc2 + p2b[tid]);
    if (n <= 0.f) s = 0.f;
    out[OFF_SS + b*D_ + tid] = s;
    red[tid] = s*s; __syncthreads();
    for (int st = 256; st; st >>= 1) { if (tid < st) red[tid] += red[tid+st]; __syncthreads(); }
    if (tid == 0) out[OFF_CN + b] = sqrtf(red[0]);
}

// ============================================================
extern "C" void kernel_launch(void* const* d_in, const int* in_sizes, int n_in,
                              void* d_out, int out_size) {
    const int*   ids   = (const int*)  d_in[0];
    const float* dur   = (const float*)d_in[1];
    const float* maskp = (const float*)d_in[2];
    const float* emb   = (const float*)d_in[3];
    const float* aux_w = (const float*)d_in[4];
    const float* aux_b = (const float*)d_in[5];
    const float* c1w   = (const float*)d_in[6];
    const float* c1b   = (const float*)d_in[7];
    const float* c2w   = (const float*)d_in[8];
    const float* c2b   = (const float*)d_in[9];
    const float* lng   = (const float*)d_in[10];
    const float* lnb   = (const float*)d_in[11];
    const float* p1w   = (const float*)d_in[12];
    const float* p1b   = (const float*)d_in[13];
    const float* p2w   = (const float*)d_in[14];
    const float* p2b   = (const float*)d_in[15];
    float* out = (float*)d_out;

    size_t shmem = 1024 + NSTAGE * BUFB;   // ~197 KB
    cudaFuncSetAttribute(k_conv_mma, cudaFuncAttributeMaxDynamicSharedMemorySize, (int)shmem);

    k_prep<<<256, 256>>>(c1w, c2w, p1w, p2w);
    k_batch_stats<<<B_, 1024>>>(dur, maskp, out);
    k_hidden0<<<(BT*(D_/4))/256, 256>>>(ids, emb, aux_w, aux_b, out);

    dim3 gconv(BT/256, D_/128);
    k_conv_mma<<<gconv, 512, shmem>>>(0, c1b);
    k_conv_mma<<<gconv, 512, shmem>>>(1, c2b);

    k_ln_stats<<<B_*16, 256>>>(lng, lnb, out);
    k_mlp<<<B_, 512>>>(p1b, p2b, out);
}

// round 16
// speedup vs baseline: 2.1575x; 1.4534x over previous
#include <cuda_runtime.h>
#include <cuda_fp16.h>
#include <math_constants.h>
#include <cstdint>

#define B_ 32
#define T_ 2048
#define D_ 512
#define BT (B_*T_)
#define BTD (BT*D_)

// ---- output layout ----
#define OFF_GR   0
#define OFF_SS   (OFF_GR + B_)
#define OFF_RM   (OFF_SS + B_*D_)
#define OFF_RV   (OFF_RM + B_)
#define OFF_COV  (OFF_RV + B_)
#define OFF_MASK (OFF_COV + B_)
#define OFF_LD   (OFF_MASK + BT)
#define OFF_REF  (OFF_LD + BT)
#define OFF_ATT  (OFF_REF + BT)
#define OFF_PRF  (OFF_ATT + BT)
#define OFF_CN   (OFF_PRF + BT)

// ---- scratch ----
__device__ __half g_x[BTD];                 // conv1 input, fp16
__device__ __half g_y[BTD];                 // conv1 output / conv2 input, fp16
__device__ float  g_h0[BTD];                // conv2 output fp32
__device__ __half g_w1[D_*3*D_];            // [o][j = k*512 + i]
__device__ __half g_w2[D_*3*D_];
__device__ float g_p1t[2*D_*D_];
__device__ float g_p2t[D_*D_];
__device__ float g_ps1[B_*16*D_];           // LN-stats partials
__device__ float g_ps2[B_*16*D_];
__device__ float g_support[B_];

__device__ __forceinline__ float gelu_f(float x) {
    return 0.5f * x * (1.0f + erff(x * 0.70710678118654752f));
}

// ============ portable PTX helpers ============
__device__ __forceinline__ uint32_t smem_u32(const void* p) {
    uint32_t a;
    asm("{ .reg .u64 t; cvta.to.shared.u64 t, %1; cvt.u32.u64 %0, t; }" : "=r"(a) : "l"(p));
    return a;
}
#define SWZ128(x) ((x) ^ (((x) >> 3) & 0x70))
__device__ __forceinline__ void cpa16(uint32_t dst, const void* src) {
    asm volatile("cp.async.cg.shared.global [%0], [%1], 16;" :: "r"(dst), "l"(src));
}
__device__ __forceinline__ void cpa_commit() { asm volatile("cp.async.commit_group;" ::: "memory"); }
__device__ __forceinline__ void cpa_wait1()  { asm volatile("cp.async.wait_group 1;" ::: "memory"); }
__device__ __forceinline__ void cpa_wait0()  { asm volatile("cp.async.wait_group 0;" ::: "memory"); }
__device__ __forceinline__ void ldsm4(uint32_t* r, uint32_t addr) {
    asm volatile("ldmatrix.sync.aligned.m8n8.x4.shared.b16 {%0,%1,%2,%3}, [%4];"
        : "=r"(r[0]), "=r"(r[1]), "=r"(r[2]), "=r"(r[3]) : "r"(addr));
}
__device__ __forceinline__ void mma_f16(float* d, const uint32_t* a, uint32_t b0, uint32_t b1) {
    asm volatile(
        "mma.sync.aligned.m16n8k16.row.col.f32.f16.f16.f32 "
        "{%0,%1,%2,%3}, {%4,%5,%6,%7}, {%8,%9}, {%0,%1,%2,%3};"
        : "+f"(d[0]), "+f"(d[1]), "+f"(d[2]), "+f"(d[3])
        : "r"(a[0]), "r"(a[1]), "r"(a[2]), "r"(a[3]), "r"(b0), "r"(b1));
}

// ============================================================
// Kernel 1: per-batch stats / median / cheap outputs
// ============================================================
__global__ void k_batch_stats(const float* __restrict__ dur,
                              const float* __restrict__ mask_in,
                              float* __restrict__ out) {
    int b = blockIdx.x, tid = threadIdx.x;
    __shared__ float sv[T_];
    __shared__ float sr[1024];
    const float* db = dur + b*T_;
    const float* mb = mask_in + b*T_;

    float accn = 0.f;
    for (int t = tid; t < T_; t += 1024) {
        float mk = fminf(fmaxf(mb[t], 0.f), 1.f);
        float ld = logf(fmaxf(db[t], 1e-4f)) * mk;
        out[OFF_MASK + b*T_ + t] = mk;
        out[OFF_LD   + b*T_ + t] = ld;
        sv[t] = (mk > 0.5f) ? ld : CUDART_INF_F;
        accn += mk;
    }
    sr[tid] = accn; __syncthreads();
    for (int s = 512; s > 0; s >>= 1) { if (tid < s) sr[tid] += sr[tid+s]; __syncthreads(); }
    float n = sr[0];
    __syncthreads();

    for (int k = 2; k <= T_; k <<= 1)
        for (int j = k >> 1; j > 0; j >>= 1) {
            for (int idx = tid; idx < T_; idx += 1024) {
                int ixj = idx ^ j;
                if (ixj > idx) {
                    float a = sv[idx], c = sv[ixj];
                    bool up = ((idx & k) == 0);
                    if ((a > c) == up) { sv[idx] = c; sv[ixj] = a; }
                }
            }
            __syncthreads();
        }

    int ni = (int)(n + 0.5f);
    float med = (ni > 0) ? sv[(ni - 1) >> 1] : 0.f;
    float support = fmaxf(n, 1.f);

    float acc1 = 0.f;
    for (int t = tid; t < T_; t += 1024) {
        float mk = out[OFF_MASK + b*T_ + t];
        float ld = out[OFF_LD   + b*T_ + t];
        float rr = (ld - med) * mk;
        out[OFF_REF + b*T_ + t] = rr;
        out[OFF_ATT + b*T_ + t] = mk / support;
        acc1 += rr;
    }
    sr[tid] = acc1; __syncthreads();
    for (int s = 512; s > 0; s >>= 1) { if (tid < s) sr[tid] += sr[tid+s]; __syncthreads(); }
    float rmean = sr[0] / support;
    __syncthreads();

    float acc2 = 0.f;
    for (int t = tid; t < T_; t += 1024) {
        float mk = out[OFF_MASK + b*T_ + t];
        float rr = out[OFF_REF  + b*T_ + t];
        float d = rr - rmean;
        acc2 += d * d * mk;
        out[OFF_PRF + b*T_ + t] = rmean * mk;
    }
    sr[tid] = acc2; __syncthreads();
    for (int s = 512; s > 0; s >>= 1) { if (tid < s) sr[tid] += sr[tid+s]; __syncthreads(); }

    if (tid == 0) {
        out[OFF_GR  + b] = med;
        out[OFF_RM  + b] = rmean;
        out[OFF_RV  + b] = fmaxf(sr[0] / support, 1e-4f);
        out[OFF_COV + b] = fmaxf(n / (float)T_, 0.05f);
        g_support[b] = n;
    }
}

// ============================================================
// Kernel 2: weight prep — fp16, layout [o][j=k*512+i]
// ============================================================
__global__ void k_prep(const float* __restrict__ c1, const float* __restrict__ c2,
                       const float* __restrict__ p1, const float* __restrict__ p2) {
    const int NW = D_*3*D_;
    const int total = 2*NW + 2*D_*D_ + D_*D_;
    for (int idx = blockIdx.x*blockDim.x + threadIdx.x; idx < total;
         idx += gridDim.x*blockDim.x) {
        if (idx < 2*NW) {
            int r = (idx < NW) ? idx : idx - NW;
            int o = r / (3*D_), j = r % (3*D_);
            int i = j & (D_-1), k = j >> 9;
            float v = (idx < NW) ? c1[o*(3*D_) + i*3 + k] : c2[o*(3*D_) + i*3 + k];
            if (idx < NW) g_w1[r] = __float2half_rn(v);
            else          g_w2[r] = __float2half_rn(v);
        } else if (idx < 2*NW + 2*D_*D_) {
            int r = idx - 2*NW;
            int j = r / D_, d = r % D_;
            g_p1t[r] = p1[d*(2*D_) + j];
        } else {
            int r = idx - (2*NW + 2*D_*D_);
            int j = r / D_, d = r % D_;
            g_p2t[r] = p2[d*D_ + j];
        }
    }
}

// ============================================================
// Kernel 3: h0 -> fp16
// ============================================================
__global__ void k_hidden0(const int* __restrict__ ids,
                          const float* __restrict__ emb,
                          const float* __restrict__ aux_w,
                          const float* __restrict__ aux_b,
                          const float* __restrict__ out) {
    int gid = blockIdx.x*blockDim.x + threadIdx.x;
    int tok = gid >> 7, dv = gid & 127;
    int id = ids[tok];
    float rr = out[OFF_REF + tok];
    float4 e = ((const float4*)emb)[id*(D_/4) + dv];
    float4 w = ((const float4*)aux_w)[dv];
    float4 bb = ((const float4*)aux_b)[dv];
    __half h[4];
    h[0] = __float2half_rn(e.x + rr*w.x + bb.x);
    h[1] = __float2half_rn(e.y + rr*w.y + bb.y);
    h[2] = __float2half_rn(e.z + rr*w.z + bb.z);
    h[3] = __float2half_rn(e.w + rr*w.w + bb.w);
    ((uint2*)g_x)[gid] = *(uint2*)h;
}

// ============================================================
// Kernel 4: causal conv via fp16 mma.sync, single pass
//   CTA 256(M) x 128(N), 512 threads (16 warps, 4x4 grid),
//   K=1536 in 24 chunks of 64, 3-stage pipeline (48KB/stage)
// ============================================================
#define CHUNKS 24
#define TA   32768                // A tile: 256 rows x 128B (fp16 X)
#define TW   16384                // W tile: 128 rows x 128B
#define AOFF 0
#define WOFF (AOFF + TA)
#define BUFB (WOFF + TW)          // 49152 per stage
#define NSTAGE 3

__global__ void __launch_bounds__(512, 1) k_conv_mma(int which, const float* __restrict__ bias) {
    const __half* X = which ? g_y  : g_x;
    const __half* W = which ? g_w2 : g_w1;

    extern __shared__ char smem_raw[];
    uint32_t sbase0 = smem_u32(smem_raw);
    uint32_t sbase = (sbase0 + 1023) & ~1023u;

    int tid = threadIdx.x;
    int wid = tid >> 5, lane = tid & 31;
    int wm = wid >> 2, wn = wid & 3;       // warp grid 4(M) x 4(N)

    int bt0   = blockIdx.x * 256;
    int o0    = blockIdx.y * 128;
    int batch = bt0 / T_;
    int tloc0 = bt0 - batch * T_;

    float acc[4][4][4] = {};

    auto load_chunk = [&](int c) {
        int j0 = c * 64;
        int kk = j0 >> 9;
        int i0 = j0 & 511;
        uint32_t bufb = sbase + (uint32_t)(c % NSTAGE) * BUFB;
        // A tile: 256 rows x 8 x 16B = 2048 transfers
        #pragma unroll
        for (int q = 0; q < 4; ++q) {
            int flat = q * 512 + tid;
            int row = flat >> 3, c16 = flat & 7;
            uint32_t swo = SWZ128((uint32_t)(row * 128 + c16 * 16));
            int st = tloc0 + row + kk - 2;
            if (st >= 0) {
                cpa16(bufb + AOFF + swo, X + (size_t)(batch*T_ + st)*D_ + i0 + c16*8);
            } else {
                *(uint4*)(smem_raw + (bufb - sbase0) + AOFF + swo) = make_uint4(0,0,0,0);
            }
        }
        // W tile: 128 rows x 8 x 16B = 1024 transfers
        #pragma unroll
        for (int q = 0; q < 2; ++q) {
            int flat = q * 512 + tid;
            int row = flat >> 3, c16 = flat & 7;
            uint32_t swo = SWZ128((uint32_t)(row * 128 + c16 * 16));
            cpa16(bufb + WOFF + swo, W + (size_t)(o0 + row)*(3*D_) + j0 + c16*8);
        }
        cpa_commit();
    };

    load_chunk(0);
    load_chunk(1);

    int lr = lane & 15;
    uint32_t L16 = (uint32_t)((lane >> 4) << 4);

    uint32_t aHo[4], bHo[2];
    #pragma unroll
    for (int mt = 0; mt < 4; ++mt) {
        uint32_t row = (uint32_t)(wm*64 + mt*16 + lr);
        aHo[mt] = AOFF + ((row * 128u) | (L16 ^ ((row & 7u) << 4)));
    }
    #pragma unroll
    for (int np = 0; np < 2; ++np) {
        uint32_t row = (uint32_t)(wn*32 + np*16 + lr);
        bHo[np] = WOFF + ((row * 128u) | (L16 ^ ((row & 7u) << 4)));
    }

    for (int c = 0; c < CHUNKS; ++c) {
        if (c + 1 < CHUNKS) cpa_wait1(); else cpa_wait0();   // chunk c resident
        __syncthreads();               // all warps done with the stage being reloaded
        if (c + 2 < CHUNKS) load_chunk(c + 2);

        uint32_t bufb = sbase + (uint32_t)(c % NSTAGE) * BUFB;
        uint32_t baH[4], bbH[2];
        #pragma unroll
        for (int mt = 0; mt < 4; ++mt) baH[mt] = bufb + aHo[mt];
        #pragma unroll
        for (int np = 0; np < 2; ++np) bbH[np] = bufb + bHo[np];

        #pragma unroll
        for (int ks = 0; ks < 4; ++ks) {
            const uint32_t Kc = (uint32_t)(ks * 32);
            uint32_t a[4][4], bh[2][4];
            #pragma unroll
            for (int mt = 0; mt < 4; ++mt) ldsm4(a[mt], baH[mt] ^ Kc);
            #pragma unroll
            for (int np = 0; np < 2; ++np) ldsm4(bh[np], bbH[np] ^ Kc);
            #pragma unroll
            for (int mt = 0; mt < 4; ++mt)
                #pragma unroll
                for (int nt = 0; nt < 4; ++nt)
                    mma_f16(acc[mt][nt], a[mt], bh[nt>>1][nt&1], bh[nt>>1][(nt&1)+2]);
        }
    }

    // ---- epilogue: bias + GELU, direct stores ----
    #pragma unroll
    for (int mt = 0; mt < 4; ++mt) {
        #pragma unroll
        for (int nt = 0; nt < 4; ++nt) {
            int row = bt0 + wm*64 + mt*16 + (lane >> 2);
            int col = o0 + wn*32 + nt*8 + (lane & 3)*2;
            float b0 = bias[col], b1 = bias[col+1];
            #pragma unroll
            for (int half = 0; half < 2; ++half) {
                int r = row + half*8;
                float y0 = gelu_f(acc[mt][nt][half*2+0] + b0);
                float y1 = gelu_f(acc[mt][nt][half*2+1] + b1);
                size_t off = (size_t)r * D_ + col;
                if (which == 0) {
                    __half h0 = __float2half_rn(y0);
                    __half h1 = __float2half_rn(y1);
                    *(__half2*)(g_y + off) = __half2(h0, h1);
                } else {
                    *(float2*)(g_h0 + off) = make_float2(y0, y1);
                }
            }
        }
    }
}

// ============================================================
// Kernel 5 (fused): LayerNorm * mask + per-channel partial stats
// ============================================================
__global__ void __launch_bounds__(256) k_ln_stats(const float* __restrict__ g,
                                                  const float* __restrict__ bta,
                                                  const float* __restrict__ out) {
    int b = blockIdx.x >> 4, chunk = blockIdx.x & 15;
    int tid = threadIdx.x, wid = tid >> 5, lane = tid & 31;
    __shared__ float s1s[8][D_];
    __shared__ float s2s[8][D_];

    float gd[16], bd[16];
    #pragma unroll
    for (int l = 0; l < 16; ++l) { gd[l] = g[l*32 + lane]; bd[l] = bta[l*32 + lane]; }

    float a1[16] = {}, a2[16] = {};
    int tokbase = b*T_ + chunk*128 + wid*16;

    for (int i = 0; i < 16; ++i) {
        int tok = tokbase + i;
        const float* x = g_h0 + (size_t)tok * D_;
        float v[16], s = 0.f;
        #pragma unroll
        for (int l = 0; l < 16; ++l) { v[l] = x[l*32 + lane]; s += v[l]; }
        #pragma unroll
        for (int o = 16; o; o >>= 1) s += __shfl_xor_sync(0xffffffffu, s, o);
        float mean = s * (1.f / D_);
        float sq = 0.f;
        #pragma unroll
        for (int l = 0; l < 16; ++l) { float d = v[l] - mean; sq += d*d; }
        #pragma unroll
        for (int o = 16; o; o >>= 1) sq += __shfl_xor_sync(0xffffffffu, sq, o);
        float inv = rsqrtf(sq * (1.f / D_) + 1e-5f);
        float mk = out[OFF_MASK + tok];
        #pragma unroll
        for (int l = 0; l < 16; ++l) {
            float y = ((v[l] - mean) * inv * gd[l] + bd[l]) * mk;
            a1[l] += y; a2[l] += y*y;
        }
    }
    #pragma unroll
    for (int l = 0; l < 16; ++l) { s1s[wid][l*32 + lane] = a1[l]; s2s[wid][l*32 + lane] = a2[l]; }
    __syncthreads();
    for (int d = tid; d < D_; d += 256) {
        float t1 = 0.f, t2 = 0.f;
        #pragma unroll
        for (int w = 0; w < 8; ++w) { t1 += s1s[w][d]; t2 += s2s[w][d]; }
        g_ps1[(b*16 + chunk)*D_ + d] = t1;
        g_ps2[(b*16 + chunk)*D_ + d] = t2;
    }
}

// ============================================================
// Kernel 6: MLP head (folds final stats reduction into prologue)
// ============================================================
__global__ void __launch_bounds__(512) k_mlp(const float* __restrict__ p1b,
                                             const float* __restrict__ p2b,
                                             float* __restrict__ out) {
    int b = blockIdx.x, tid = threadIdx.x;
    __shared__ float h[1024];
    __shared__ float a[512];
    __shared__ float red[512];

    float S1 = 0.f, S2 = 0.f;
    #pragma unroll
    for (int c = 0; c < 16; ++c) {
        S1 += g_ps1[(b*16 + c)*D_ + tid];
        S2 += g_ps2[(b*16 + c)*D_ + tid];
    }
    float n = g_support[b];
    float denom = fmaxf(n, 1.f);
    float mean = S1 / denom;
    float varsum = S2 - 2.f*mean*S1 + mean*mean*n;
    h[tid]       = mean;
    h[tid + 512] = sqrtf(varsum / denom + 1e-6f);
    __syncthreads();

    float acc = 0.f;
    #pragma unroll 4
    for (int j = 0; j < 1024; ++j) acc += h[j] * g_p1t[j*D_ + tid];
    a[tid] = gelu_f(acc + p1b[tid]);
    __syncthreads();
    float acc2 = 0.f;
    #pragma unroll 4
    for (int j = 0; j < 512; ++j) acc2 += a[j] * g_p2t[j*D_ + tid];
    float s = tanhf(acc2 + p2b[tid]);
    if (n <= 0.f) s = 0.f;
    out[OFF_SS + b*D_ + tid] = s;
    red[tid] = s*s; __syncthreads();
    for (int st = 256; st; st >>= 1) { if (tid < st) red[tid] += red[tid+st]; __syncthreads(); }
    if (tid == 0) out[OFF_CN + b] = sqrtf(red[0]);
}

// ============================================================
extern "C" void kernel_launch(void* const* d_in, const int* in_sizes, int n_in,
                              void* d_out, int out_size) {
    const int*   ids   = (const int*)  d_in[0];
    const float* dur   = (const float*)d_in[1];
    const float* maskp = (const float*)d_in[2];
    const float* emb   = (const float*)d_in[3];
    const float* aux_w = (const float*)d_in[4];
    const float* aux_b = (const float*)d_in[5];
    const float* c1w   = (const float*)d_in[6];
    const float* c1b   = (const float*)d_in[7];
    const float* c2w   = (const float*)d_in[8];
    const float* c2b   = (const float*)d_in[9];
    const float* lng   = (const float*)d_in[10];
    const float* lnb   = (const float*)d_in[11];
    const float* p1w   = (const float*)d_in[12];
    const float* p1b   = (const float*)d_in[13];
    const float* p2w   = (const float*)d_in[14];
    const float* p2b   = (const float*)d_in[15];
    float* out = (float*)d_out;

    size_t shmem = 1024 + NSTAGE * BUFB;   // ~145 KB
    cudaFuncSetAttribute(k_conv_mma, cudaFuncAttributeMaxDynamicSharedMemorySize, (int)shmem);

    k_prep<<<256, 256>>>(c1w, c2w, p1w, p2w);
    k_batch_stats<<<B_, 1024>>>(dur, maskp, out);
    k_hidden0<<<(BT*(D_/4))/256, 256>>>(ids, emb, aux_w, aux_b, out);

    dim3 gconv(BT/256, D_/128);
    k_conv_mma<<<gconv, 512, shmem>>>(0, c1b);
    k_conv_mma<<<gconv, 512, shmem>>>(1, c2b);

    k_ln_stats<<<B_*16, 256>>>(lng, lnb, out);
    k_mlp<<<B_, 512>>>(p1b, p2b, out);
}